// round 1
// baseline (speedup 1.0000x reference)
#include <cuda_runtime.h>

// NAryTreeLSTMCell fused kernel — round 1 (fp32 SIMT baseline).
// ARITY=2, LABEL_DIM=128, H_DIM=512, B=16384, ARG_DIM=1152.
// Computes 5 fused GEMMs (i, o, u, f0, f1) over the virtual concatenated
// x = [label | h0 | h1] and virtual Wf = [W_fl | W_fs[k,0] | W_fs[k,1]],
// then the full LSTM epilogue, writing (next_cell, out) concatenated.

namespace {
constexpr int Bsz = 16384;
constexpr int H   = 512;
constexpr int L   = 128;
constexpr int K   = 1152;   // L + 2*H
constexpr int BM  = 64;
constexpr int BN  = 32;
constexpr int BK  = 16;
constexpr int NG  = 5;
constexpr int THREADS = 256;
constexpr int BMp = BM + 4;   // pad: conflict-reduced STS, keeps float4 LDS aligned
constexpr int BNp = BN + 2;   // pad: conflict-free STS, keeps float2 LDS aligned

__device__ __forceinline__ float sigmoidf_(float x) {
    return 1.0f / (1.0f + __expf(-x));
}
} // namespace

__global__ __launch_bounds__(THREADS)
void treelstm_fused(
    const float* __restrict__ label,
    const float* __restrict__ ch_h,
    const float* __restrict__ ch_c,
    const float* __restrict__ W_i, const float* __restrict__ b_i,
    const float* __restrict__ W_o, const float* __restrict__ b_o,
    const float* __restrict__ W_u, const float* __restrict__ b_u,
    const float* __restrict__ W_fl, const float* __restrict__ W_fs,
    const float* __restrict__ fbias,
    float* __restrict__ out)
{
    __shared__ float As[BK][BMp];        // x tile, transposed (k-major)
    __shared__ float Bs[NG][BK][BNp];    // 5 weight tiles, transposed

    const int tid = threadIdx.x;
    const int bm0 = blockIdx.x * BM;
    const int bn0 = blockIdx.y * BN;
    const int tx  = tid & 15;            // 16 col-groups (2 cols each)
    const int ty  = tid >> 4;            // 16 row-groups (4 rows each)
    const int m_base = ty * 4;
    const int n_base = tx * 2;

    float acc[NG][8];
    #pragma unroll
    for (int g = 0; g < NG; g++)
        #pragma unroll
        for (int i = 0; i < 8; i++) acc[g][i] = 0.0f;

    const int arow = tid >> 2;           // 0..63 : batch row within tile
    const int aq   = tid & 3;            // quad within BK=16

    for (int k0 = 0; k0 < K; k0 += BK) {
        // ---- stage A tile: gather x = [label | h0 | h1] (one float4/thread) ----
        {
            const int b = bm0 + arow;
            const float* src;
            if (k0 < L) {
                src = label + (size_t)b * L + k0 + aq * 4;
            } else {
                const int j   = (k0 - L) >> 9;                 // which child
                const int hin = (k0 - L) - (j << 9) + aq * 4;  // offset in h
                src = ch_h + (((size_t)(j * Bsz + b)) << 9) + hin;
            }
            const float4 v = *reinterpret_cast<const float4*>(src);
            As[aq*4+0][arow] = v.x;
            As[aq*4+1][arow] = v.y;
            As[aq*4+2][arow] = v.z;
            As[aq*4+3][arow] = v.w;
        }
        // ---- stage B tiles: 5 gates x 32 rows x 16 k (640 float4 / 256 thr) ----
        for (int i = tid; i < NG * BN * (BK/4); i += THREADS) {
            const int g = i >> 7;         // gate 0..4
            const int r = i & 127;
            const int n = r >> 2;         // 0..31 : h-out within tile
            const int q = r & 3;          // quad within BK
            const int hout = bn0 + n;
            const float* src;
            if (g == 0) {
                src = W_i + (size_t)hout * K + k0 + q * 4;
            } else if (g == 1) {
                src = W_o + (size_t)hout * K + k0 + q * 4;
            } else if (g == 2) {
                src = W_u + (size_t)hout * K + k0 + q * 4;
            } else {
                const int kc = g - 3;     // which forget child
                if (k0 < L) {
                    src = W_fl + (size_t)hout * L + k0 + q * 4;
                } else {
                    const int j   = (k0 - L) >> 9;
                    const int hin = (k0 - L) - (j << 9) + q * 4;
                    // W_fs[kc, j, hout, hin]
                    src = W_fs + (((size_t)(((kc*2 + j) << 9) + hout)) << 9) + hin;
                }
            }
            const float4 v = *reinterpret_cast<const float4*>(src);
            Bs[g][q*4+0][n] = v.x;
            Bs[g][q*4+1][n] = v.y;
            Bs[g][q*4+2][n] = v.z;
            Bs[g][q*4+3][n] = v.w;
        }
        __syncthreads();
        // ---- compute: 4x2 micro-tile per thread, per gate ----
        #pragma unroll
        for (int kk = 0; kk < BK; kk++) {
            const float4 a4 = *reinterpret_cast<const float4*>(&As[kk][m_base]);
            const float av[4] = {a4.x, a4.y, a4.z, a4.w};
            #pragma unroll
            for (int g = 0; g < NG; g++) {
                const float2 bv = *reinterpret_cast<const float2*>(&Bs[g][kk][n_base]);
                #pragma unroll
                for (int im = 0; im < 4; im++) {
                    acc[g][im*2+0] = fmaf(av[im], bv.x, acc[g][im*2+0]);
                    acc[g][im*2+1] = fmaf(av[im], bv.y, acc[g][im*2+1]);
                }
            }
        }
        __syncthreads();
    }

    // ---- fused LSTM epilogue ----
    #pragma unroll
    for (int in = 0; in < 2; in++) {
        const int h = bn0 + n_base + in;
        const float bi = b_i[h];
        const float bo = b_o[h];
        const float bu = b_u[h];
        const float fb = fbias[h];
        #pragma unroll
        for (int im = 0; im < 4; im++) {
            const int b   = bm0 + m_base + im;
            const int idx = im*2 + in;
            const float ig = sigmoidf_(acc[0][idx] + bi);
            const float og = sigmoidf_(acc[1][idx] + bo);
            const float ug = tanhf(acc[2][idx] + bu);
            const float f0 = sigmoidf_(acc[3][idx]);
            const float f1 = sigmoidf_(acc[4][idx]);
            const float c0 = ch_c[(size_t)b * H + h];
            const float c1 = ch_c[(size_t)(Bsz + b) * H + h];
            const float nc = fmaf(ig, ug, fmaf(f0, c0, fmaf(f1, c1, fb * (c0 + c1))));
            out[(size_t)b * H + h] = nc;                                // next_cell
            out[(size_t)Bsz * H + (size_t)b * H + h] = tanhf(og * nc);  // out
        }
    }
}

extern "C" void kernel_launch(void* const* d_in, const int* in_sizes, int n_in,
                              void* d_out, int out_size) {
    const float* label = (const float*)d_in[0];
    const float* ch_h  = (const float*)d_in[1];
    const float* ch_c  = (const float*)d_in[2];
    const float* W_i   = (const float*)d_in[3];
    const float* b_i   = (const float*)d_in[4];
    const float* W_o   = (const float*)d_in[5];
    const float* b_o   = (const float*)d_in[6];
    const float* W_u   = (const float*)d_in[7];
    const float* b_u   = (const float*)d_in[8];
    const float* W_fl  = (const float*)d_in[9];
    const float* W_fs  = (const float*)d_in[10];
    const float* fb    = (const float*)d_in[11];

    dim3 grid(Bsz / BM, H / BN);   // 256 x 16
    treelstm_fused<<<grid, THREADS>>>(label, ch_h, ch_c,
                                      W_i, b_i, W_o, b_o, W_u, b_u,
                                      W_fl, W_fs, fb, (float*)d_out);
}

// round 3
// speedup vs baseline: 1.7171x; 1.7171x over previous
#include <cuda_runtime.h>
#include <cuda_bf16.h>
#include <cstdint>

// NAryTreeLSTMCell — round 3: bf16 3-split GEMM on mma.sync (family-common PTX,
// works at compute_103 target; tcgen05 is sm_103a-only and rejected by harness).
// ARITY=2, LABEL_DIM=128, H_DIM=512, B=16384, ARG_DIM=1152.

namespace {
constexpr int Bsz = 16384;
constexpr int H   = 512;
constexpr int L   = 128;
constexpr int K   = 1152;
constexpr int NG  = 5;
constexpr int BM  = 64;            // batch rows / CTA
constexpr int BH  = 64;            // h per gate / CTA  (N_total = 320)
constexpr int BK  = 64;            // K per chunk (128B bf16 rows, SW128)
constexpr int NCHUNK = K / BK;     // 18
constexpr int THREADS = 320;       // 10 warps: 2 (m) x 5 (gate)

// stage layout (bytes from stage base)
constexpr uint32_t OFF_AHI = 0;                    //  64 x 128B = 8KB
constexpr uint32_t OFF_ALO = 8192;
constexpr uint32_t OFF_BHI = 16384;                // 320 x 128B = 40KB
constexpr uint32_t OFF_BLO = 57344;
constexpr uint32_t STAGE_BYTES = 98304;            // 96KB
constexpr uint32_t SMEM_DATA0 = 1024;
constexpr uint32_t SMEM_TOTAL = SMEM_DATA0 + 2 * STAGE_BYTES;   // 197632
} // namespace

// ---- scratch (module globals; no runtime allocation) ----
__device__ __nv_bfloat16 g_Xhi[(size_t)Bsz * K];
__device__ __nv_bfloat16 g_Xlo[(size_t)Bsz * K];
__device__ __nv_bfloat16 g_Whi[(size_t)NG * H * K];
__device__ __nv_bfloat16 g_Wlo[(size_t)NG * H * K];

// ---- PTX helpers (all family-common: sm_80+) ----
__device__ __forceinline__ uint32_t smem_u32(const void* p) {
    return (uint32_t)__cvta_generic_to_shared(p);
}
__device__ __forceinline__ void cp16(uint32_t s, const void* g) {
    asm volatile("cp.async.cg.shared.global [%0], [%1], 16;\n" :: "r"(s), "l"(g));
}
__device__ __forceinline__ void cp_commit() {
    asm volatile("cp.async.commit_group;\n" ::: "memory");
}
template <int N> __device__ __forceinline__ void cp_wait() {
    asm volatile("cp.async.wait_group %0;\n" :: "n"(N) : "memory");
}
__device__ __forceinline__ void ldsm4(uint32_t* r, uint32_t a) {
    asm volatile("ldmatrix.sync.aligned.m8n8.x4.shared.b16 {%0,%1,%2,%3}, [%4];"
                 : "=r"(r[0]), "=r"(r[1]), "=r"(r[2]), "=r"(r[3]) : "r"(a));
}
__device__ __forceinline__ void mma_bf16(float* c, const uint32_t* a, const uint32_t* b) {
    asm volatile("mma.sync.aligned.m16n8k16.row.col.f32.bf16.bf16.f32 "
                 "{%0,%1,%2,%3}, {%4,%5,%6,%7}, {%8,%9}, {%0,%1,%2,%3};"
                 : "+f"(c[0]), "+f"(c[1]), "+f"(c[2]), "+f"(c[3])
                 : "r"(a[0]), "r"(a[1]), "r"(a[2]), "r"(a[3]), "r"(b[0]), "r"(b[1]));
}
__device__ __forceinline__ uint32_t swz(uint32_t o) { return o ^ ((o >> 3) & 0x70); }
__device__ __forceinline__ float sigmf(float x) { return 1.0f / (1.0f + __expf(-x)); }

// ---- pack kernels: fp32 -> bf16 hi/lo splits with virtual concats ----
__global__ void pack_x(const float* __restrict__ label, const float* __restrict__ ch_h) {
    int i = blockIdx.x * blockDim.x + threadIdx.x;      // over Bsz * (K/4)
    if (i >= Bsz * (K / 4)) return;
    int b = i / (K / 4);
    int d = (i % (K / 4)) * 4;
    const float* src;
    if (d < L) src = label + (size_t)b * L + d;
    else {
        int dd = d - L; int j = dd >> 9; int hh = dd & 511;
        src = ch_h + (((size_t)(j * Bsz + b)) << 9) + hh;
    }
    float4 v = *reinterpret_cast<const float4*>(src);
    __nv_bfloat16 hi[4], lo[4];
    float vv[4] = {v.x, v.y, v.z, v.w};
    #pragma unroll
    for (int t = 0; t < 4; t++) {
        hi[t] = __float2bfloat16(vv[t]);
        lo[t] = __float2bfloat16(vv[t] - __bfloat162float(hi[t]));
    }
    size_t o = (size_t)b * K + d;
    *reinterpret_cast<uint2*>(&g_Xhi[o]) = *reinterpret_cast<uint2*>(hi);
    *reinterpret_cast<uint2*>(&g_Xlo[o]) = *reinterpret_cast<uint2*>(lo);
}

__global__ void pack_w(const float* __restrict__ Wi, const float* __restrict__ Wo,
                       const float* __restrict__ Wu, const float* __restrict__ Wfl,
                       const float* __restrict__ Wfs) {
    int i = blockIdx.x * blockDim.x + threadIdx.x;      // over NG*H*(K/4)
    if (i >= NG * H * (K / 4)) return;
    int r = i / (K / 4);
    int d = (i % (K / 4)) * 4;
    int g = r >> 9, h = r & 511;
    const float* src;
    if (g == 0)      src = Wi + (size_t)h * K + d;
    else if (g == 1) src = Wo + (size_t)h * K + d;
    else if (g == 2) src = Wu + (size_t)h * K + d;
    else if (d < L)  src = Wfl + (size_t)h * L + d;
    else {
        int dd = d - L; int j = dd >> 9; int hh = dd & 511;
        src = Wfs + (((size_t)(((g - 3) * 2 + j) * H + h)) << 9) + hh;
    }
    float4 v = *reinterpret_cast<const float4*>(src);
    __nv_bfloat16 hi[4], lo[4];
    float vv[4] = {v.x, v.y, v.z, v.w};
    #pragma unroll
    for (int t = 0; t < 4; t++) {
        hi[t] = __float2bfloat16(vv[t]);
        lo[t] = __float2bfloat16(vv[t] - __bfloat162float(hi[t]));
    }
    size_t o = (size_t)r * K + d;
    *reinterpret_cast<uint2*>(&g_Whi[o]) = *reinterpret_cast<uint2*>(hi);
    *reinterpret_cast<uint2*>(&g_Wlo[o]) = *reinterpret_cast<uint2*>(lo);
}

// ---- chunk loader: gmem bf16 -> swizzled SMEM tiles (6144 x 16B) ----
__device__ __forceinline__ void load_chunk(int k0, uint32_t stg, int bm0, int bh0, int tid) {
    for (int i = tid; i < 6144; i += THREADS) {
        if (i < 1024) {                       // A: 2 splits x 64 rows x 8 chunks
            int which = i >> 9;               // 0 = hi, 1 = lo
            int t = i & 511;
            int r = t >> 3, c = t & 7;
            const __nv_bfloat16* base = which ? g_Xlo : g_Xhi;
            const void* ga = base + (size_t)(bm0 + r) * K + k0 + c * 8;
            cp16(stg + (which ? OFF_ALO : OFF_AHI) + swz(r * 128 + c * 16), ga);
        } else {                              // B: 2 splits x 320 rows x 8 chunks
            int u = i - 1024;
            int which = u >= 2560;
            int v = which ? u - 2560 : u;
            int r = v >> 3, c = v & 7;        // r in [0,320)
            int grow = (r >> 6) * H + bh0 + (r & 63);
            const __nv_bfloat16* base = which ? g_Wlo : g_Whi;
            const void* ga = base + (size_t)grow * K + k0 + c * 8;
            cp16(stg + (which ? OFF_BLO : OFF_BHI) + swz(r * 128 + c * 16), ga);
        }
    }
}

// ---- main kernel ----
__global__ __launch_bounds__(THREADS, 1)
void treelstm_mma(const float* __restrict__ ch_c,
                  const float* __restrict__ b_i, const float* __restrict__ b_o,
                  const float* __restrict__ b_u, const float* __restrict__ fbias,
                  float* __restrict__ out) {
    extern __shared__ char smem[];
    const uint32_t sbase = smem_u32(smem);
    const int tid  = threadIdx.x;
    const int wid  = tid >> 5, lane = tid & 31;
    const int wm   = wid & 1;          // m half (0/1)
    const int g    = wid >> 1;         // gate 0..4
    const int bh0  = blockIdx.x * BH;
    const int bm0  = blockIdx.y * BM;

    const uint32_t STG0 = sbase + SMEM_DATA0;
    const uint32_t STG1 = STG0 + STAGE_BYTES;

    float acc[2][8][4];
    #pragma unroll
    for (int mi = 0; mi < 2; mi++)
        #pragma unroll
        for (int ni = 0; ni < 8; ni++)
            #pragma unroll
            for (int q = 0; q < 4; q++) acc[mi][ni][q] = 0.0f;

    load_chunk(0, STG0, bm0, bh0, tid);  cp_commit();
    load_chunk(BK, STG1, bm0, bh0, tid); cp_commit();

    // per-lane ldmatrix row/col components (constant across chunks)
    const int arow = wm * 32 + ((lane >> 3) & 1) * 8 + (lane & 7);
    const int akb  = (lane >> 4) * 16;
    const int brow0 = g * 64 + ((lane >> 4) & 1) * 8 + (lane & 7);
    const int bkb  = ((lane >> 3) & 1) * 16;

    for (int k = 0; k < NCHUNK; k++) {
        const uint32_t stg = (k & 1) ? STG1 : STG0;
        if (k < NCHUNK - 1) cp_wait<1>(); else cp_wait<0>();
        __syncthreads();

        #pragma unroll
        for (int ks = 0; ks < 4; ks++) {
            uint32_t ahi[2][4], alo[2][4];
            #pragma unroll
            for (int mi = 0; mi < 2; mi++) {
                const uint32_t ao = swz((arow + mi * 16) * 128 + ks * 32 + akb);
                ldsm4(ahi[mi], stg + OFF_AHI + ao);
                ldsm4(alo[mi], stg + OFF_ALO + ao);
            }
            #pragma unroll
            for (int np = 0; np < 4; np++) {
                uint32_t bhi[4], blo[4];
                const uint32_t bo = swz((brow0 + np * 16) * 128 + ks * 32 + bkb);
                ldsm4(bhi, stg + OFF_BHI + bo);
                ldsm4(blo, stg + OFF_BLO + bo);
                #pragma unroll
                for (int mi = 0; mi < 2; mi++) {
                    mma_bf16(acc[mi][2*np+0], ahi[mi], bhi + 0);
                    mma_bf16(acc[mi][2*np+0], ahi[mi], blo + 0);
                    mma_bf16(acc[mi][2*np+0], alo[mi], bhi + 0);
                    mma_bf16(acc[mi][2*np+1], ahi[mi], bhi + 2);
                    mma_bf16(acc[mi][2*np+1], ahi[mi], blo + 2);
                    mma_bf16(acc[mi][2*np+1], alo[mi], bhi + 2);
                }
            }
        }
        __syncthreads();
        if (k + 2 < NCHUNK) {
            load_chunk((k + 2) * BK, stg, bm0, bh0, tid);
            cp_commit();
        }
    }

    // ---- epilogue: recombine 5 gates per (m,h) through SMEM ----
    __syncthreads();
    float* gbuf = reinterpret_cast<float*>(smem + SMEM_DATA0);   // [5][64][66]

    #pragma unroll
    for (int mi = 0; mi < 2; mi++)
        #pragma unroll
        for (int ni = 0; ni < 8; ni++) {
            const int row = wm * 32 + mi * 16 + (lane >> 2);
            const int col = ni * 8 + 2 * (lane & 3);
            float* p0 = gbuf + ((size_t)g * 64 + row) * 66 + col;
            p0[0] = acc[mi][ni][0];
            p0[1] = acc[mi][ni][1];
            float* p1 = gbuf + ((size_t)g * 64 + row + 8) * 66 + col;
            p1[0] = acc[mi][ni][2];
            p1[1] = acc[mi][ni][3];
        }
    __syncthreads();

    for (int idx = tid; idx < BM * BH; idx += THREADS) {
        const int m = idx >> 6, h = idx & 63;
        const int hg = bh0 + h;
        const int b  = bm0 + m;
        const float vi = gbuf[(0 * 64 + m) * 66 + h];
        const float vo = gbuf[(1 * 64 + m) * 66 + h];
        const float vu = gbuf[(2 * 64 + m) * 66 + h];
        const float v0 = gbuf[(3 * 64 + m) * 66 + h];
        const float v1 = gbuf[(4 * 64 + m) * 66 + h];
        const float ig = sigmf(vi + __ldg(&b_i[hg]));
        const float og = sigmf(vo + __ldg(&b_o[hg]));
        const float ug = tanhf(vu + __ldg(&b_u[hg]));
        const float f0 = sigmf(v0);
        const float f1 = sigmf(v1);
        const float c0 = ch_c[(size_t)b * H + hg];
        const float c1 = ch_c[(size_t)(Bsz + b) * H + hg];
        const float fb = __ldg(&fbias[hg]);
        const float nc = fmaf(ig, ug, fmaf(f0, c0, fmaf(f1, c1, fb * (c0 + c1))));
        const size_t o = (size_t)b * H + hg;
        out[o] = nc;
        out[(size_t)Bsz * H + o] = tanhf(og * nc);
    }
}

extern "C" void kernel_launch(void* const* d_in, const int* in_sizes, int n_in,
                              void* d_out, int out_size) {
    const float* label = (const float*)d_in[0];
    const float* ch_h  = (const float*)d_in[1];
    const float* ch_c  = (const float*)d_in[2];
    const float* W_i   = (const float*)d_in[3];
    const float* b_i   = (const float*)d_in[4];
    const float* W_o   = (const float*)d_in[5];
    const float* b_o   = (const float*)d_in[6];
    const float* W_u   = (const float*)d_in[7];
    const float* b_u   = (const float*)d_in[8];
    const float* W_fl  = (const float*)d_in[9];
    const float* W_fs  = (const float*)d_in[10];
    const float* fb    = (const float*)d_in[11];

    pack_x<<<(Bsz * (K / 4) + 255) / 256, 256>>>(label, ch_h);
    pack_w<<<(NG * H * (K / 4) + 255) / 256, 256>>>(W_i, W_o, W_u, W_fl, W_fs);

    cudaFuncSetAttribute(treelstm_mma, cudaFuncAttributeMaxDynamicSharedMemorySize, SMEM_TOTAL);
    dim3 grid(H / BH, Bsz / BM);   // (8, 256) — h-tile fastest: weights stay L2-hot
    treelstm_mma<<<grid, THREADS, SMEM_TOTAL>>>(ch_c, b_i, b_o, b_u, fb, (float*)d_out);
}

// round 4
// speedup vs baseline: 1.8021x; 1.0495x over previous
#include <cuda_runtime.h>
#include <cuda_bf16.h>
#include <cstdint>

// NAryTreeLSTMCell — round 4: bf16 3-split mma.sync, pass-ordered accumulation,
// granule-blocked SMEM (conflict-free ldmatrix, no swizzle math), 512-thread CTA.
// ARITY=2, LABEL_DIM=128, H_DIM=512, B=16384, ARG_DIM=1152.

namespace {
constexpr int Bsz = 16384;
constexpr int H   = 512;
constexpr int L   = 128;
constexpr int K   = 1152;
constexpr int NG  = 5;
constexpr int BM  = 128;           // batch rows / CTA
constexpr int BNR = 320;           // B rows: 5 gates x 64 h
constexpr int BHh = 64;            // h per gate per CTA
constexpr int BK  = 64;
constexpr int NCHUNK = K / BK;     // 18
constexpr int THREADS = 512;       // 16 warps: 4(m) x 4(n)

// granule-blocked layout: addr = OFF + g*(ROWS*16) + r*16, g in [0,8) (8 k-elems each)
constexpr uint32_t AG = BM * 16;    // 2048
constexpr uint32_t BG = BNR * 16;   // 5120
constexpr uint32_t OFF_AHI = 0;
constexpr uint32_t OFF_ALO = 16384;
constexpr uint32_t OFF_BHI = 32768;
constexpr uint32_t OFF_BLO = 73728;
constexpr uint32_t STAGE_BYTES = 114688;          // 112KB
constexpr uint32_t SMEM_TOTAL  = 2 * STAGE_BYTES; // 229376 (<= 232448)
} // namespace

// ---- scratch (module globals) ----
__device__ __nv_bfloat16 g_Xhi[(size_t)Bsz * K];
__device__ __nv_bfloat16 g_Xlo[(size_t)Bsz * K];
__device__ __nv_bfloat16 g_Whi[(size_t)NG * H * K];
__device__ __nv_bfloat16 g_Wlo[(size_t)NG * H * K];

// ---- PTX helpers (family-common, sm_80+) ----
__device__ __forceinline__ uint32_t smem_u32(const void* p) {
    return (uint32_t)__cvta_generic_to_shared(p);
}
__device__ __forceinline__ void cp16(uint32_t s, const void* g) {
    asm volatile("cp.async.cg.shared.global [%0], [%1], 16;\n" :: "r"(s), "l"(g));
}
__device__ __forceinline__ void cp_commit() {
    asm volatile("cp.async.commit_group;\n" ::: "memory");
}
template <int N> __device__ __forceinline__ void cp_wait() {
    asm volatile("cp.async.wait_group %0;\n" :: "n"(N) : "memory");
}
__device__ __forceinline__ void ldsm4(uint32_t* r, uint32_t a) {
    asm volatile("ldmatrix.sync.aligned.m8n8.x4.shared.b16 {%0,%1,%2,%3}, [%4];"
                 : "=r"(r[0]), "=r"(r[1]), "=r"(r[2]), "=r"(r[3]) : "r"(a));
}
__device__ __forceinline__ void mma_bf16(float* c, const uint32_t* a, const uint32_t* b) {
    asm volatile("mma.sync.aligned.m16n8k16.row.col.f32.bf16.bf16.f32 "
                 "{%0,%1,%2,%3}, {%4,%5,%6,%7}, {%8,%9}, {%0,%1,%2,%3};"
                 : "+f"(c[0]), "+f"(c[1]), "+f"(c[2]), "+f"(c[3])
                 : "r"(a[0]), "r"(a[1]), "r"(a[2]), "r"(a[3]), "r"(b[0]), "r"(b[1]));
}
__device__ __forceinline__ float sigmf(float x) { return 1.0f / (1.0f + __expf(-x)); }

// ---- pack kernels: fp32 -> bf16 hi/lo splits with virtual concats ----
__global__ void pack_x(const float* __restrict__ label, const float* __restrict__ ch_h) {
    int i = blockIdx.x * blockDim.x + threadIdx.x;      // over Bsz * (K/4)
    if (i >= Bsz * (K / 4)) return;
    int b = i / (K / 4);
    int d = (i % (K / 4)) * 4;
    const float* src;
    if (d < L) src = label + (size_t)b * L + d;
    else {
        int dd = d - L; int j = dd >> 9; int hh = dd & 511;
        src = ch_h + (((size_t)(j * Bsz + b)) << 9) + hh;
    }
    float4 v = *reinterpret_cast<const float4*>(src);
    __nv_bfloat16 hi[4], lo[4];
    float vv[4] = {v.x, v.y, v.z, v.w};
    #pragma unroll
    for (int t = 0; t < 4; t++) {
        hi[t] = __float2bfloat16(vv[t]);
        lo[t] = __float2bfloat16(vv[t] - __bfloat162float(hi[t]));
    }
    size_t o = (size_t)b * K + d;
    *reinterpret_cast<uint2*>(&g_Xhi[o]) = *reinterpret_cast<uint2*>(hi);
    *reinterpret_cast<uint2*>(&g_Xlo[o]) = *reinterpret_cast<uint2*>(lo);
}

__global__ void pack_w(const float* __restrict__ Wi, const float* __restrict__ Wo,
                       const float* __restrict__ Wu, const float* __restrict__ Wfl,
                       const float* __restrict__ Wfs) {
    int i = blockIdx.x * blockDim.x + threadIdx.x;      // over NG*H*(K/4)
    if (i >= NG * H * (K / 4)) return;
    int r = i / (K / 4);
    int d = (i % (K / 4)) * 4;
    int g = r >> 9, h = r & 511;
    const float* src;
    if (g == 0)      src = Wi + (size_t)h * K + d;
    else if (g == 1) src = Wo + (size_t)h * K + d;
    else if (g == 2) src = Wu + (size_t)h * K + d;
    else if (d < L)  src = Wfl + (size_t)h * L + d;
    else {
        int dd = d - L; int j = dd >> 9; int hh = dd & 511;
        src = Wfs + (((size_t)(((g - 3) * 2 + j) * H + h)) << 9) + hh;
    }
    float4 v = *reinterpret_cast<const float4*>(src);
    __nv_bfloat16 hi[4], lo[4];
    float vv[4] = {v.x, v.y, v.z, v.w};
    #pragma unroll
    for (int t = 0; t < 4; t++) {
        hi[t] = __float2bfloat16(vv[t]);
        lo[t] = __float2bfloat16(vv[t] - __bfloat162float(hi[t]));
    }
    size_t o = (size_t)r * K + d;
    *reinterpret_cast<uint2*>(&g_Whi[o]) = *reinterpret_cast<uint2*>(hi);
    *reinterpret_cast<uint2*>(&g_Wlo[o]) = *reinterpret_cast<uint2*>(lo);
}

// ---- chunk loader: 7168 x 16B granules, fully coalesced ----
__device__ __forceinline__ void load_chunk(int k0, uint32_t stg, int bm0, int bh0, int tid) {
    #pragma unroll
    for (int it = 0; it < 14; it++) {
        int idx = tid + it * THREADS;
        if (idx < 2048) {                          // A: 2 splits x 128 rows x 8 granules
            int which = idx >> 10;
            int t = idx & 1023;
            int r = t >> 3, g = t & 7;
            const __nv_bfloat16* base = which ? g_Xlo : g_Xhi;
            cp16(stg + (which ? OFF_ALO : OFF_AHI) + g * AG + r * 16,
                 base + (size_t)(bm0 + r) * K + k0 + g * 8);
        } else {                                   // B: 2 splits x 320 rows x 8 granules
            int u = idx - 2048;
            int which = u >= 2560;
            int v = which ? u - 2560 : u;
            int r = v >> 3, g = v & 7;
            int grow = (r >> 6) * H + bh0 + (r & 63);
            const __nv_bfloat16* base = which ? g_Wlo : g_Whi;
            cp16(stg + (which ? OFF_BLO : OFF_BHI) + g * BG + r * 16,
                 base + (size_t)grow * K + k0 + g * 8);
        }
    }
}

// ---- main kernel ----
__global__ __launch_bounds__(THREADS, 1)
void treelstm_mma(const float* __restrict__ ch_c,
                  const float* __restrict__ b_i, const float* __restrict__ b_o,
                  const float* __restrict__ b_u, const float* __restrict__ fbias,
                  float* __restrict__ out) {
    extern __shared__ char smem[];
    const uint32_t sbase = smem_u32(smem);
    const int tid  = threadIdx.x;
    const int wid  = tid >> 5, lane = tid & 31;
    const int wm   = wid & 3;          // 4 m-warps (32 rows each)
    const int wn   = wid >> 2;         // 4 n-warps (80 cols each)
    const int bh0  = blockIdx.x * BHh;
    const int bm0  = blockIdx.y * BM;

    const uint32_t STG0 = sbase;
    const uint32_t STG1 = sbase + STAGE_BYTES;

    // per-lane ldmatrix base offsets (granule-blocked layout, no swizzle)
    const int ar  = ((lane >> 3) & 1) * 8 + (lane & 7);
    const uint32_t aBase = (uint32_t)((wm * 32 + ar) * 16) + (uint32_t)(lane >> 4) * AG;
    const int br  = ((lane >> 4) & 1) * 8 + (lane & 7);
    const uint32_t bBase = (uint32_t)((wn * 80 + br) * 16) + (uint32_t)((lane >> 3) & 1) * BG;

    float acc[2][10][4];
    #pragma unroll
    for (int mi = 0; mi < 2; mi++)
        #pragma unroll
        for (int ni = 0; ni < 10; ni++)
            #pragma unroll
            for (int q = 0; q < 4; q++) acc[mi][ni][q] = 0.0f;

    load_chunk(0, STG0, bm0, bh0, tid);  cp_commit();
    load_chunk(BK, STG1, bm0, bh0, tid); cp_commit();

    for (int k = 0; k < NCHUNK; k++) {
        const uint32_t stg = (k & 1) ? STG1 : STG0;
        if (k < NCHUNK - 1) cp_wait<1>(); else cp_wait<0>();
        __syncthreads();

        #pragma unroll
        for (int ks = 0; ks < 4; ks++) {
            const uint32_t aAddr = stg + aBase + (uint32_t)(2 * ks) * AG;
            const uint32_t bAddr = stg + bBase + (uint32_t)(2 * ks) * BG;
            uint32_t ahi[8], alo[8];
            ldsm4(ahi + 0, aAddr + OFF_AHI);
            ldsm4(ahi + 4, aAddr + OFF_AHI + 256);   // mi=1: +16 rows * 16B
            ldsm4(alo + 0, aAddr + OFF_ALO);
            ldsm4(alo + 4, aAddr + OFF_ALO + 256);
            // pass 1: A_hi * B_hi
            #pragma unroll
            for (int np = 0; np < 5; np++) {
                uint32_t b[4];
                ldsm4(b, bAddr + OFF_BHI + np * 256);
                mma_bf16(acc[0][np*2+0], ahi + 0, b + 0);
                mma_bf16(acc[0][np*2+1], ahi + 0, b + 2);
                mma_bf16(acc[1][np*2+0], ahi + 4, b + 0);
                mma_bf16(acc[1][np*2+1], ahi + 4, b + 2);
            }
            // pass 2: A_hi * B_lo
            #pragma unroll
            for (int np = 0; np < 5; np++) {
                uint32_t b[4];
                ldsm4(b, bAddr + OFF_BLO + np * 256);
                mma_bf16(acc[0][np*2+0], ahi + 0, b + 0);
                mma_bf16(acc[0][np*2+1], ahi + 0, b + 2);
                mma_bf16(acc[1][np*2+0], ahi + 4, b + 0);
                mma_bf16(acc[1][np*2+1], ahi + 4, b + 2);
            }
            // pass 3: A_lo * B_hi
            #pragma unroll
            for (int np = 0; np < 5; np++) {
                uint32_t b[4];
                ldsm4(b, bAddr + OFF_BHI + np * 256);
                mma_bf16(acc[0][np*2+0], alo + 0, b + 0);
                mma_bf16(acc[0][np*2+1], alo + 0, b + 2);
                mma_bf16(acc[1][np*2+0], alo + 4, b + 0);
                mma_bf16(acc[1][np*2+1], alo + 4, b + 2);
            }
        }
        __syncthreads();
        if (k + 2 < NCHUNK) {
            load_chunk((k + 2) * BK, stg, bm0, bh0, tid);
            cp_commit();
        }
    }

    // ---- epilogue: recombine gates through SMEM (stride 129 words, conflict-free) ----
    float* gbuf = reinterpret_cast<float*>(smem);   // [320][129]
    #pragma unroll
    for (int mi = 0; mi < 2; mi++)
        #pragma unroll
        for (int ni = 0; ni < 10; ni++) {
            const int m = wm * 32 + mi * 16 + (lane >> 2);
            const int n = wn * 80 + ni * 8 + 2 * (lane & 3);
            gbuf[(size_t)n * 129 + m]           = acc[mi][ni][0];
            gbuf[(size_t)(n + 1) * 129 + m]     = acc[mi][ni][1];
            gbuf[(size_t)n * 129 + m + 8]       = acc[mi][ni][2];
            gbuf[(size_t)(n + 1) * 129 + m + 8] = acc[mi][ni][3];
        }
    __syncthreads();

    for (int idx = tid; idx < BM * BHh; idx += THREADS) {
        const int m = idx >> 6, h = idx & 63;
        const int hg = bh0 + h;
        const int b  = bm0 + m;
        const float vi = gbuf[(size_t)(0 * 64 + h) * 129 + m];
        const float vo = gbuf[(size_t)(1 * 64 + h) * 129 + m];
        const float vu = gbuf[(size_t)(2 * 64 + h) * 129 + m];
        const float v0 = gbuf[(size_t)(3 * 64 + h) * 129 + m];
        const float v1 = gbuf[(size_t)(4 * 64 + h) * 129 + m];
        const float ig = sigmf(vi + __ldg(&b_i[hg]));
        const float og = sigmf(vo + __ldg(&b_o[hg]));
        const float ug = tanhf(vu + __ldg(&b_u[hg]));
        const float f0 = sigmf(v0);
        const float f1 = sigmf(v1);
        const float c0 = ch_c[(size_t)b * H + hg];
        const float c1 = ch_c[(size_t)(Bsz + b) * H + hg];
        const float fb = __ldg(&fbias[hg]);
        const float nc = fmaf(ig, ug, fmaf(f0, c0, fmaf(f1, c1, fb * (c0 + c1))));
        const size_t o = (size_t)b * H + hg;
        out[o] = nc;
        out[(size_t)Bsz * H + o] = tanhf(og * nc);
    }
}

extern "C" void kernel_launch(void* const* d_in, const int* in_sizes, int n_in,
                              void* d_out, int out_size) {
    const float* label = (const float*)d_in[0];
    const float* ch_h  = (const float*)d_in[1];
    const float* ch_c  = (const float*)d_in[2];
    const float* W_i   = (const float*)d_in[3];
    const float* b_i   = (const float*)d_in[4];
    const float* W_o   = (const float*)d_in[5];
    const float* b_o   = (const float*)d_in[6];
    const float* W_u   = (const float*)d_in[7];
    const float* b_u   = (const float*)d_in[8];
    const float* W_fl  = (const float*)d_in[9];
    const float* W_fs  = (const float*)d_in[10];
    const float* fb    = (const float*)d_in[11];

    pack_x<<<(Bsz * (K / 4) + 255) / 256, 256>>>(label, ch_h);
    pack_w<<<(NG * H * (K / 4) + 255) / 256, 256>>>(W_i, W_o, W_u, W_fl, W_fs);

    cudaFuncSetAttribute(treelstm_mma, cudaFuncAttributeMaxDynamicSharedMemorySize, SMEM_TOTAL);
    dim3 grid(H / BHh, Bsz / BM);   // (8, 128) — h fastest: A tiles shared via L2
    treelstm_mma<<<grid, THREADS, SMEM_TOTAL>>>(ch_c, b_i, b_o, b_u, fb, (float*)d_out);
}

// round 5
// speedup vs baseline: 2.5322x; 1.4051x over previous
#include <cuda_runtime.h>
#include <cuda_fp16.h>
#include <cstdint>

// NAryTreeLSTMCell — round 5: single-pass fp16 mma.sync (3x fewer HMMA than the
// bf16 3-split; legacy HMMA pipe on sm_103a measured at rt~16/SMSP is the wall).
// ARITY=2, LABEL_DIM=128, H_DIM=512, B=16384, ARG_DIM=1152.

namespace {
constexpr int Bsz = 16384;
constexpr int H   = 512;
constexpr int L   = 128;
constexpr int K   = 1152;
constexpr int NG  = 5;
constexpr int BM  = 128;           // batch rows / CTA
constexpr int BNR = 320;           // B rows: 5 gates x 64 h
constexpr int BHh = 64;            // h per gate per CTA
constexpr int BK  = 128;           // K per chunk
constexpr int NCHUNK = K / BK;     // 9
constexpr int THREADS = 512;       // 16 warps: 4(m) x 4(n)

// granule-blocked layout: addr = OFF + g*(ROWS*16) + r*16, g in [0,16)
constexpr uint32_t AG = BM * 16;    // 2048
constexpr uint32_t BG = BNR * 16;   // 5120
constexpr uint32_t OFF_A = 0;                      // 128 x 256B = 32KB
constexpr uint32_t OFF_B = 32768;                  // 320 x 256B = 80KB
constexpr uint32_t STAGE_BYTES = 114688;           // 112KB
constexpr uint32_t SMEM_TOTAL  = 2 * STAGE_BYTES;  // 229376
} // namespace

// ---- scratch (module globals) ----
__device__ __half g_Xf[(size_t)Bsz * K];
__device__ __half g_Wf[(size_t)NG * H * K];

// ---- PTX helpers (family-common, sm_80+) ----
__device__ __forceinline__ uint32_t smem_u32(const void* p) {
    return (uint32_t)__cvta_generic_to_shared(p);
}
__device__ __forceinline__ void cp16(uint32_t s, const void* g) {
    asm volatile("cp.async.cg.shared.global [%0], [%1], 16;\n" :: "r"(s), "l"(g));
}
__device__ __forceinline__ void cp_commit() {
    asm volatile("cp.async.commit_group;\n" ::: "memory");
}
template <int N> __device__ __forceinline__ void cp_wait() {
    asm volatile("cp.async.wait_group %0;\n" :: "n"(N) : "memory");
}
__device__ __forceinline__ void ldsm4(uint32_t* r, uint32_t a) {
    asm volatile("ldmatrix.sync.aligned.m8n8.x4.shared.b16 {%0,%1,%2,%3}, [%4];"
                 : "=r"(r[0]), "=r"(r[1]), "=r"(r[2]), "=r"(r[3]) : "r"(a));
}
__device__ __forceinline__ void mma_f16(float* c, const uint32_t* a, const uint32_t* b) {
    asm volatile("mma.sync.aligned.m16n8k16.row.col.f32.f16.f16.f32 "
                 "{%0,%1,%2,%3}, {%4,%5,%6,%7}, {%8,%9}, {%0,%1,%2,%3};"
                 : "+f"(c[0]), "+f"(c[1]), "+f"(c[2]), "+f"(c[3])
                 : "r"(a[0]), "r"(a[1]), "r"(a[2]), "r"(a[3]), "r"(b[0]), "r"(b[1]));
}
__device__ __forceinline__ float sigmf(float x) { return 1.0f / (1.0f + __expf(-x)); }

// ---- pack kernels: fp32 -> fp16 with virtual concats ----
__global__ void pack_x(const float* __restrict__ label, const float* __restrict__ ch_h) {
    int i = blockIdx.x * blockDim.x + threadIdx.x;      // over Bsz * (K/4)
    if (i >= Bsz * (K / 4)) return;
    int b = i / (K / 4);
    int d = (i % (K / 4)) * 4;
    const float* src;
    if (d < L) src = label + (size_t)b * L + d;
    else {
        int dd = d - L; int j = dd >> 9; int hh = dd & 511;
        src = ch_h + (((size_t)(j * Bsz + b)) << 9) + hh;
    }
    float4 v = *reinterpret_cast<const float4*>(src);
    __half h4[4] = {__float2half_rn(v.x), __float2half_rn(v.y),
                    __float2half_rn(v.z), __float2half_rn(v.w)};
    *reinterpret_cast<uint2*>(&g_Xf[(size_t)b * K + d]) = *reinterpret_cast<uint2*>(h4);
}

__global__ void pack_w(const float* __restrict__ Wi, const float* __restrict__ Wo,
                       const float* __restrict__ Wu, const float* __restrict__ Wfl,
                       const float* __restrict__ Wfs) {
    int i = blockIdx.x * blockDim.x + threadIdx.x;      // over NG*H*(K/4)
    if (i >= NG * H * (K / 4)) return;
    int r = i / (K / 4);
    int d = (i % (K / 4)) * 4;
    int g = r >> 9, h = r & 511;
    const float* src;
    if (g == 0)      src = Wi + (size_t)h * K + d;
    else if (g == 1) src = Wo + (size_t)h * K + d;
    else if (g == 2) src = Wu + (size_t)h * K + d;
    else if (d < L)  src = Wfl + (size_t)h * L + d;
    else {
        int dd = d - L; int j = dd >> 9; int hh = dd & 511;
        src = Wfs + (((size_t)(((g - 3) * 2 + j) * H + h)) << 9) + hh;
    }
    float4 v = *reinterpret_cast<const float4*>(src);
    __half h4[4] = {__float2half_rn(v.x), __float2half_rn(v.y),
                    __float2half_rn(v.z), __float2half_rn(v.w)};
    *reinterpret_cast<uint2*>(&g_Wf[(size_t)r * K + d]) = *reinterpret_cast<uint2*>(h4);
}

// ---- chunk loader: 7168 x 16B granules, coalesced ----
__device__ __forceinline__ void load_chunk(int k0, uint32_t stg, int bm0, int bh0, int tid) {
    #pragma unroll
    for (int it = 0; it < 14; it++) {
        int idx = tid + it * THREADS;
        if (idx < 2048) {                          // A: 128 rows x 16 granules
            int r = idx >> 4, g = idx & 15;
            cp16(stg + OFF_A + g * AG + r * 16,
                 g_Xf + (size_t)(bm0 + r) * K + k0 + g * 8);
        } else {                                   // B: 320 rows x 16 granules
            int u = idx - 2048;
            int r = u >> 4, g = u & 15;
            int grow = (r >> 6) * H + bh0 + (r & 63);
            cp16(stg + OFF_B + g * BG + r * 16,
                 g_Wf + (size_t)grow * K + k0 + g * 8);
        }
    }
}

// ---- main kernel ----
__global__ __launch_bounds__(THREADS, 1)
void treelstm_mma(const float* __restrict__ ch_c,
                  const float* __restrict__ b_i, const float* __restrict__ b_o,
                  const float* __restrict__ b_u, const float* __restrict__ fbias,
                  float* __restrict__ out) {
    extern __shared__ char smem[];
    const uint32_t sbase = smem_u32(smem);
    const int tid  = threadIdx.x;
    const int wid  = tid >> 5, lane = tid & 31;
    const int wm   = wid & 3;          // 4 m-warps (32 rows each)
    const int wn   = wid >> 2;         // 4 n-warps (80 cols each)
    const int bh0  = blockIdx.x * BHh;
    const int bm0  = blockIdx.y * BM;

    const uint32_t STG0 = sbase;
    const uint32_t STG1 = sbase + STAGE_BYTES;

    // per-lane ldmatrix base offsets (granule-blocked, no swizzle)
    const int ar  = ((lane >> 3) & 1) * 8 + (lane & 7);
    const uint32_t aBase = (uint32_t)((wm * 32 + ar) * 16) + (uint32_t)(lane >> 4) * AG;
    const int br  = ((lane >> 4) & 1) * 8 + (lane & 7);
    const uint32_t bBase = (uint32_t)((wn * 80 + br) * 16) + (uint32_t)((lane >> 3) & 1) * BG;

    float acc[2][10][4];
    #pragma unroll
    for (int mi = 0; mi < 2; mi++)
        #pragma unroll
        for (int ni = 0; ni < 10; ni++)
            #pragma unroll
            for (int q = 0; q < 4; q++) acc[mi][ni][q] = 0.0f;

    load_chunk(0, STG0, bm0, bh0, tid);  cp_commit();
    load_chunk(BK, STG1, bm0, bh0, tid); cp_commit();

    for (int k = 0; k < NCHUNK; k++) {
        const uint32_t stg = (k & 1) ? STG1 : STG0;
        if (k < NCHUNK - 1) cp_wait<1>(); else cp_wait<0>();
        __syncthreads();

        #pragma unroll
        for (int ks = 0; ks < 8; ks++) {           // 8 k16 steps per 128-K chunk
            const uint32_t aAddr = stg + OFF_A + aBase + (uint32_t)(2 * ks) * AG;
            const uint32_t bAddr = stg + OFF_B + bBase + (uint32_t)(2 * ks) * BG;
            uint32_t a[8];
            ldsm4(a + 0, aAddr);
            ldsm4(a + 4, aAddr + 256);             // mi=1: +16 rows * 16B
            uint32_t b[20];
            #pragma unroll
            for (int np = 0; np < 5; np++)
                ldsm4(b + np * 4, bAddr + np * 256);
            #pragma unroll
            for (int np = 0; np < 5; np++) {
                mma_f16(acc[0][np*2+0], a + 0, b + np*4 + 0);
                mma_f16(acc[0][np*2+1], a + 0, b + np*4 + 2);
                mma_f16(acc[1][np*2+0], a + 4, b + np*4 + 0);
                mma_f16(acc[1][np*2+1], a + 4, b + np*4 + 2);
            }
        }
        __syncthreads();
        if (k + 2 < NCHUNK) {
            load_chunk((k + 2) * BK, stg, bm0, bh0, tid);
            cp_commit();
        }
    }

    // ---- epilogue: recombine gates through SMEM (stride 129 words) ----
    __syncthreads();
    float* gbuf = reinterpret_cast<float*>(smem);   // [320][129]
    #pragma unroll
    for (int mi = 0; mi < 2; mi++)
        #pragma unroll
        for (int ni = 0; ni < 10; ni++) {
            const int m = wm * 32 + mi * 16 + (lane >> 2);
            const int n = wn * 80 + ni * 8 + 2 * (lane & 3);
            gbuf[(size_t)n * 129 + m]           = acc[mi][ni][0];
            gbuf[(size_t)(n + 1) * 129 + m]     = acc[mi][ni][1];
            gbuf[(size_t)n * 129 + m + 8]       = acc[mi][ni][2];
            gbuf[(size_t)(n + 1) * 129 + m + 8] = acc[mi][ni][3];
        }
    __syncthreads();

    for (int idx = tid; idx < BM * BHh; idx += THREADS) {
        const int m = idx >> 6, h = idx & 63;
        const int hg = bh0 + h;
        const int b  = bm0 + m;
        const float vi = gbuf[(size_t)(0 * 64 + h) * 129 + m];
        const float vo = gbuf[(size_t)(1 * 64 + h) * 129 + m];
        const float vu = gbuf[(size_t)(2 * 64 + h) * 129 + m];
        const float v0 = gbuf[(size_t)(3 * 64 + h) * 129 + m];
        const float v1 = gbuf[(size_t)(4 * 64 + h) * 129 + m];
        const float ig = sigmf(vi + __ldg(&b_i[hg]));
        const float og = sigmf(vo + __ldg(&b_o[hg]));
        const float ug = tanhf(vu + __ldg(&b_u[hg]));
        const float f0 = sigmf(v0);
        const float f1 = sigmf(v1);
        const float c0 = ch_c[(size_t)b * H + hg];
        const float c1 = ch_c[(size_t)(Bsz + b) * H + hg];
        const float fb = __ldg(&fbias[hg]);
        const float nc = fmaf(ig, ug, fmaf(f0, c0, fmaf(f1, c1, fb * (c0 + c1))));
        const size_t o = (size_t)b * H + hg;
        out[o] = nc;
        out[(size_t)Bsz * H + o] = tanhf(og * nc);
    }
}

extern "C" void kernel_launch(void* const* d_in, const int* in_sizes, int n_in,
                              void* d_out, int out_size) {
    const float* label = (const float*)d_in[0];
    const float* ch_h  = (const float*)d_in[1];
    const float* ch_c  = (const float*)d_in[2];
    const float* W_i   = (const float*)d_in[3];
    const float* b_i   = (const float*)d_in[4];
    const float* W_o   = (const float*)d_in[5];
    const float* b_o   = (const float*)d_in[6];
    const float* W_u   = (const float*)d_in[7];
    const float* b_u   = (const float*)d_in[8];
    const float* W_fl  = (const float*)d_in[9];
    const float* W_fs  = (const float*)d_in[10];
    const float* fb    = (const float*)d_in[11];

    pack_x<<<(Bsz * (K / 4) + 255) / 256, 256>>>(label, ch_h);
    pack_w<<<(NG * H * (K / 4) + 255) / 256, 256>>>(W_i, W_o, W_u, W_fl, W_fs);

    cudaFuncSetAttribute(treelstm_mma, cudaFuncAttributeMaxDynamicSharedMemorySize, SMEM_TOTAL);
    dim3 grid(H / BHh, Bsz / BM);   // (8, 128)
    treelstm_mma<<<grid, THREADS, SMEM_TOTAL>>>(ch_c, b_i, b_o, b_u, fb, (float*)d_out);
}

// round 6
// speedup vs baseline: 3.7106x; 1.4654x over previous
#include <cuda_runtime.h>
#include <cuda_fp16.h>
#include <cstdint>

// NAryTreeLSTMCell — round 6: fp16 single-pass mma.sync with short B live ranges
// (round 5 bulk-loaded 20 B regs -> reg-cap pressure at 512 thr / 128 regs).
// ARITY=2, LABEL_DIM=128, H_DIM=512, B=16384, ARG_DIM=1152.

namespace {
constexpr int Bsz = 16384;
constexpr int H   = 512;
constexpr int L   = 128;
constexpr int K   = 1152;
constexpr int NG  = 5;
constexpr int BM  = 128;           // batch rows / CTA
constexpr int BNR = 320;           // B rows: 5 gates x 64 h
constexpr int BHh = 64;            // h per gate per CTA
constexpr int BK  = 128;           // K per chunk
constexpr int NCHUNK = K / BK;     // 9
constexpr int THREADS = 512;       // 16 warps: 4(m) x 4(n)

// granule-blocked layout: addr = OFF + g*(ROWS*16) + r*16, g in [0,16)
constexpr uint32_t AG = BM * 16;    // 2048
constexpr uint32_t BG = BNR * 16;   // 5120
constexpr uint32_t OFF_A = 0;                      // 128 x 256B = 32KB
constexpr uint32_t OFF_B = 32768;                  // 320 x 256B = 80KB
constexpr uint32_t STAGE_BYTES = 114688;           // 112KB
constexpr uint32_t SMEM_TOTAL  = 2 * STAGE_BYTES;  // 229376
} // namespace

// ---- scratch (module globals) ----
__device__ __half g_Xf[(size_t)Bsz * K];
__device__ __half g_Wf[(size_t)NG * H * K];

// ---- PTX helpers (family-common, sm_80+) ----
__device__ __forceinline__ uint32_t smem_u32(const void* p) {
    return (uint32_t)__cvta_generic_to_shared(p);
}
__device__ __forceinline__ void cp16(uint32_t s, const void* g) {
    asm volatile("cp.async.cg.shared.global [%0], [%1], 16;\n" :: "r"(s), "l"(g));
}
__device__ __forceinline__ void cp_commit() {
    asm volatile("cp.async.commit_group;\n" ::: "memory");
}
template <int N> __device__ __forceinline__ void cp_wait() {
    asm volatile("cp.async.wait_group %0;\n" :: "n"(N) : "memory");
}
__device__ __forceinline__ void ldsm4(uint32_t* r, uint32_t a) {
    asm volatile("ldmatrix.sync.aligned.m8n8.x4.shared.b16 {%0,%1,%2,%3}, [%4];"
                 : "=r"(r[0]), "=r"(r[1]), "=r"(r[2]), "=r"(r[3]) : "r"(a));
}
__device__ __forceinline__ void mma_f16(float* c, const uint32_t* a, const uint32_t* b) {
    asm volatile("mma.sync.aligned.m16n8k16.row.col.f32.f16.f16.f32 "
                 "{%0,%1,%2,%3}, {%4,%5,%6,%7}, {%8,%9}, {%0,%1,%2,%3};"
                 : "+f"(c[0]), "+f"(c[1]), "+f"(c[2]), "+f"(c[3])
                 : "r"(a[0]), "r"(a[1]), "r"(a[2]), "r"(a[3]), "r"(b[0]), "r"(b[1]));
}
__device__ __forceinline__ float sigmf(float x) { return 1.0f / (1.0f + __expf(-x)); }

// ---- pack kernels: fp32 -> fp16 with virtual concats ----
__global__ void pack_x(const float* __restrict__ label, const float* __restrict__ ch_h) {
    int i = blockIdx.x * blockDim.x + threadIdx.x;      // over Bsz * (K/4)
    if (i >= Bsz * (K / 4)) return;
    int b = i / (K / 4);
    int d = (i % (K / 4)) * 4;
    const float* src;
    if (d < L) src = label + (size_t)b * L + d;
    else {
        int dd = d - L; int j = dd >> 9; int hh = dd & 511;
        src = ch_h + (((size_t)(j * Bsz + b)) << 9) + hh;
    }
    float4 v = *reinterpret_cast<const float4*>(src);
    __half h4[4] = {__float2half_rn(v.x), __float2half_rn(v.y),
                    __float2half_rn(v.z), __float2half_rn(v.w)};
    *reinterpret_cast<uint2*>(&g_Xf[(size_t)b * K + d]) = *reinterpret_cast<uint2*>(h4);
}

__global__ void pack_w(const float* __restrict__ Wi, const float* __restrict__ Wo,
                       const float* __restrict__ Wu, const float* __restrict__ Wfl,
                       const float* __restrict__ Wfs) {
    int i = blockIdx.x * blockDim.x + threadIdx.x;      // over NG*H*(K/4)
    if (i >= NG * H * (K / 4)) return;
    int r = i / (K / 4);
    int d = (i % (K / 4)) * 4;
    int g = r >> 9, h = r & 511;
    const float* src;
    if (g == 0)      src = Wi + (size_t)h * K + d;
    else if (g == 1) src = Wo + (size_t)h * K + d;
    else if (g == 2) src = Wu + (size_t)h * K + d;
    else if (d < L)  src = Wfl + (size_t)h * L + d;
    else {
        int dd = d - L; int j = dd >> 9; int hh = dd & 511;
        src = Wfs + (((size_t)(((g - 3) * 2 + j) * H + h)) << 9) + hh;
    }
    float4 v = *reinterpret_cast<const float4*>(src);
    __half h4[4] = {__float2half_rn(v.x), __float2half_rn(v.y),
                    __float2half_rn(v.z), __float2half_rn(v.w)};
    *reinterpret_cast<uint2*>(&g_Wf[(size_t)r * K + d]) = *reinterpret_cast<uint2*>(h4);
}

// ---- chunk loader: 7168 x 16B granules, coalesced ----
__device__ __forceinline__ void load_chunk(int k0, uint32_t stg, int bm0, int bh0, int tid) {
    #pragma unroll
    for (int it = 0; it < 14; it++) {
        int idx = tid + it * THREADS;
        if (idx < 2048) {                          // A: 128 rows x 16 granules
            int r = idx >> 4, g = idx & 15;
            cp16(stg + OFF_A + g * AG + r * 16,
                 g_Xf + (size_t)(bm0 + r) * K + k0 + g * 8);
        } else {                                   // B: 320 rows x 16 granules
            int u = idx - 2048;
            int r = u >> 4, g = u & 15;
            int grow = (r >> 6) * H + bh0 + (r & 63);
            cp16(stg + OFF_B + g * BG + r * 16,
                 g_Wf + (size_t)grow * K + k0 + g * 8);
        }
    }
}

// ---- main kernel ----
__global__ __launch_bounds__(THREADS, 1)
void treelstm_mma(const float* __restrict__ ch_c,
                  const float* __restrict__ b_i, const float* __restrict__ b_o,
                  const float* __restrict__ b_u, const float* __restrict__ fbias,
                  float* __restrict__ out) {
    extern __shared__ char smem[];
    const uint32_t sbase = smem_u32(smem);
    const int tid  = threadIdx.x;
    const int wid  = tid >> 5, lane = tid & 31;
    const int wm   = wid & 3;          // 4 m-warps (32 rows each)
    const int wn   = wid >> 2;         // 4 n-warps (80 cols each)
    const int bh0  = blockIdx.x * BHh;
    const int bm0  = blockIdx.y * BM;

    const uint32_t STG0 = sbase;
    const uint32_t STG1 = sbase + STAGE_BYTES;

    // per-lane ldmatrix base offsets (granule-blocked, no swizzle)
    const int ar  = ((lane >> 3) & 1) * 8 + (lane & 7);
    const uint32_t aBase = (uint32_t)((wm * 32 + ar) * 16) + (uint32_t)(lane >> 4) * AG;
    const int br  = ((lane >> 4) & 1) * 8 + (lane & 7);
    const uint32_t bBase = (uint32_t)((wn * 80 + br) * 16) + (uint32_t)((lane >> 3) & 1) * BG;

    float acc[2][10][4];
    #pragma unroll
    for (int mi = 0; mi < 2; mi++)
        #pragma unroll
        for (int ni = 0; ni < 10; ni++)
            #pragma unroll
            for (int q = 0; q < 4; q++) acc[mi][ni][q] = 0.0f;

    load_chunk(0, STG0, bm0, bh0, tid);  cp_commit();
    load_chunk(BK, STG1, bm0, bh0, tid); cp_commit();

    for (int k = 0; k < NCHUNK; k++) {
        const uint32_t stg = (k & 1) ? STG1 : STG0;
        if (k < NCHUNK - 1) cp_wait<1>(); else cp_wait<0>();
        __syncthreads();

        #pragma unroll
        for (int ks = 0; ks < 8; ks++) {           // 8 k16 steps per 128-K chunk
            const uint32_t aAddr = stg + OFF_A + aBase + (uint32_t)(2 * ks) * AG;
            const uint32_t bAddr = stg + OFF_B + bBase + (uint32_t)(2 * ks) * BG;
            uint32_t a[8];
            ldsm4(a + 0, aAddr);
            ldsm4(a + 4, aAddr + 256);             // mi=1: +16 rows * 16B
            // per-np load-then-use: only 4 B regs live at a time (reg budget!)
            #pragma unroll
            for (int np = 0; np < 5; np++) {
                uint32_t b[4];
                ldsm4(b, bAddr + np * 256);
                mma_f16(acc[0][np*2+0], a + 0, b + 0);
                mma_f16(acc[0][np*2+1], a + 0, b + 2);
                mma_f16(acc[1][np*2+0], a + 4, b + 0);
                mma_f16(acc[1][np*2+1], a + 4, b + 2);
            }
        }
        __syncthreads();
        if (k + 2 < NCHUNK) {
            load_chunk((k + 2) * BK, stg, bm0, bh0, tid);
            cp_commit();
        }
    }

    // ---- epilogue: recombine gates through SMEM (stride 129 words) ----
    __syncthreads();
    float* gbuf = reinterpret_cast<float*>(smem);   // [320][129]
    #pragma unroll
    for (int mi = 0; mi < 2; mi++)
        #pragma unroll
        for (int ni = 0; ni < 10; ni++) {
            const int m = wm * 32 + mi * 16 + (lane >> 2);
            const int n = wn * 80 + ni * 8 + 2 * (lane & 3);
            gbuf[(size_t)n * 129 + m]           = acc[mi][ni][0];
            gbuf[(size_t)(n + 1) * 129 + m]     = acc[mi][ni][1];
            gbuf[(size_t)n * 129 + m + 8]       = acc[mi][ni][2];
            gbuf[(size_t)(n + 1) * 129 + m + 8] = acc[mi][ni][3];
        }
    __syncthreads();

    for (int idx = tid; idx < BM * BHh; idx += THREADS) {
        const int m = idx >> 6, h = idx & 63;
        const int hg = bh0 + h;
        const int b  = bm0 + m;
        const float vi = gbuf[(size_t)(0 * 64 + h) * 129 + m];
        const float vo = gbuf[(size_t)(1 * 64 + h) * 129 + m];
        const float vu = gbuf[(size_t)(2 * 64 + h) * 129 + m];
        const float v0 = gbuf[(size_t)(3 * 64 + h) * 129 + m];
        const float v1 = gbuf[(size_t)(4 * 64 + h) * 129 + m];
        const float ig = sigmf(vi + __ldg(&b_i[hg]));
        const float og = sigmf(vo + __ldg(&b_o[hg]));
        const float ug = tanhf(vu + __ldg(&b_u[hg]));
        const float f0 = sigmf(v0);
        const float f1 = sigmf(v1);
        const float c0 = ch_c[(size_t)b * H + hg];
        const float c1 = ch_c[(size_t)(Bsz + b) * H + hg];
        const float fb = __ldg(&fbias[hg]);
        const float nc = fmaf(ig, ug, fmaf(f0, c0, fmaf(f1, c1, fb * (c0 + c1))));
        const size_t o = (size_t)b * H + hg;
        out[o] = nc;
        out[(size_t)Bsz * H + o] = tanhf(og * nc);
    }
}

extern "C" void kernel_launch(void* const* d_in, const int* in_sizes, int n_in,
                              void* d_out, int out_size) {
    const float* label = (const float*)d_in[0];
    const float* ch_h  = (const float*)d_in[1];
    const float* ch_c  = (const float*)d_in[2];
    const float* W_i   = (const float*)d_in[3];
    const float* b_i   = (const float*)d_in[4];
    const float* W_o   = (const float*)d_in[5];
    const float* b_o   = (const float*)d_in[6];
    const float* W_u   = (const float*)d_in[7];
    const float* b_u   = (const float*)d_in[8];
    const float* W_fl  = (const float*)d_in[9];
    const float* W_fs  = (const float*)d_in[10];
    const float* fb    = (const float*)d_in[11];

    pack_x<<<(Bsz * (K / 4) + 255) / 256, 256>>>(label, ch_h);
    pack_w<<<(NG * H * (K / 4) + 255) / 256, 256>>>(W_i, W_o, W_u, W_fl, W_fs);

    cudaFuncSetAttribute(treelstm_mma, cudaFuncAttributeMaxDynamicSharedMemorySize, SMEM_TOTAL);
    dim3 grid(H / BHh, Bsz / BM);   // (8, 128)
    treelstm_mma<<<grid, THREADS, SMEM_TOTAL>>>(ch_c, b_i, b_o, b_u, fb, (float*)d_out);
}

// round 8
// speedup vs baseline: 6.2113x; 1.6739x over previous
#include <cuda_runtime.h>
#include <cuda_fp16.h>
#include <cstdint>

// NAryTreeLSTMCell — round 7: fp16 mma.sync + cp.async.bulk (UBLKCP) tile loads.
// Round 6 was LSU-issue-bound: 7168 cp.async(16B) per chunk (~129k cyc/SMSP/CTA)
// vs 92k cyc of HMMA. Bulk DMA copies remove the LSU issue cost entirely.
// Pack kernels write gmem in the exact SMEM tile image (chunk-tiled, granule-
// blocked) so one linear bulk copy per operand per chunk suffices.
// ARITY=2, LABEL_DIM=128, H_DIM=512, B=16384, ARG_DIM=1152.

namespace {
constexpr int Bsz = 16384;
constexpr int H   = 512;
constexpr int L   = 128;
constexpr int K   = 1152;
constexpr int NG  = 5;
constexpr int BM  = 128;           // batch rows / CTA
constexpr int BNR = 320;           // B rows: 5 gates x 64 h
constexpr int BHh = 64;            // h per gate per CTA
constexpr int BK  = 128;           // K per chunk
constexpr int NCHUNK = K / BK;     // 9
constexpr int THREADS = 512;       // 16 warps: 4(m) x 4(n)

// granule-blocked tile image: addr = g*(ROWS*16) + r*16, g in [0,16)
constexpr uint32_t AG = BM * 16;    // 2048
constexpr uint32_t BG = BNR * 16;   // 5120
constexpr uint32_t A_TILE = 16 * AG;               // 32768 B
constexpr uint32_t B_TILE = 16 * BG;               // 81920 B
constexpr uint32_t OFF_A = 0;
constexpr uint32_t OFF_B = A_TILE;
constexpr uint32_t STAGE_BYTES = A_TILE + B_TILE;  // 114688
constexpr uint32_t SMEM_TOTAL  = 2 * STAGE_BYTES + 64;  // + mbarriers
} // namespace

// ---- scratch: chunk-tiled, granule-blocked images (exact SMEM layout) ----
__device__ __half g_Xt[(size_t)NCHUNK * (Bsz / BM) * (A_TILE / 2)];
__device__ __half g_Wt[(size_t)NCHUNK * (H / BHh) * (B_TILE / 2)];

// ---- PTX helpers ----
__device__ __forceinline__ uint32_t smem_u32(const void* p) {
    return (uint32_t)__cvta_generic_to_shared(p);
}
__device__ __forceinline__ void bulk_cp(uint32_t dst, const void* src,
                                        uint32_t bytes, uint32_t mbar) {
    asm volatile("cp.async.bulk.shared::cta.global.mbarrier::complete_tx::bytes "
                 "[%0], [%1], %2, [%3];"
                 :: "r"(dst), "l"(src), "r"(bytes), "r"(mbar) : "memory");
}
__device__ __forceinline__ void mbar_init(uint32_t a, uint32_t cnt) {
    asm volatile("mbarrier.init.shared.b64 [%0], %1;" :: "r"(a), "r"(cnt) : "memory");
}
__device__ __forceinline__ void mbar_expect(uint32_t a, uint32_t bytes) {
    asm volatile("mbarrier.arrive.expect_tx.shared::cta.b64 _, [%0], %1;"
                 :: "r"(a), "r"(bytes) : "memory");
}
__device__ __forceinline__ void mbar_wait(uint32_t a, uint32_t ph) {
    asm volatile("{\n.reg .pred P;\nLW%=:\n"
                 "mbarrier.try_wait.parity.shared::cta.b64 P, [%0], %1;\n"
                 "@!P bra LW%=;\n}" :: "r"(a), "r"(ph) : "memory");
}
__device__ __forceinline__ void ldsm4(uint32_t* r, uint32_t a) {
    asm volatile("ldmatrix.sync.aligned.m8n8.x4.shared.b16 {%0,%1,%2,%3}, [%4];"
                 : "=r"(r[0]), "=r"(r[1]), "=r"(r[2]), "=r"(r[3]) : "r"(a));
}
__device__ __forceinline__ void mma_f16(float* c, const uint32_t* a, const uint32_t* b) {
    asm volatile("mma.sync.aligned.m16n8k16.row.col.f32.f16.f16.f32 "
                 "{%0,%1,%2,%3}, {%4,%5,%6,%7}, {%8,%9}, {%0,%1,%2,%3};"
                 : "+f"(c[0]), "+f"(c[1]), "+f"(c[2]), "+f"(c[3])
                 : "r"(a[0]), "r"(a[1]), "r"(a[2]), "r"(a[3]), "r"(b[0]), "r"(b[1]));
}
__device__ __forceinline__ float sigmf(float x) { return 1.0f / (1.0f + __expf(-x)); }

// ---- pack kernels: fp32 -> fp16, writing the granule-blocked tile image ----
__global__ void pack_x(const float* __restrict__ label, const float* __restrict__ ch_h) {
    int i = blockIdx.x * blockDim.x + threadIdx.x;      // over Bsz * (K/4)
    if (i >= Bsz * (K / 4)) return;
    int b = i / (K / 4);
    int d = (i % (K / 4)) * 4;
    const float* src;
    if (d < L) src = label + (size_t)b * L + d;
    else {
        int dd = d - L; int j = dd >> 9; int hh = dd & 511;
        src = ch_h + (((size_t)(j * Bsz + b)) << 9) + hh;
    }
    float4 v = *reinterpret_cast<const float4*>(src);
    __half h4[4] = {__float2half_rn(v.x), __float2half_rn(v.y),
                    __float2half_rn(v.z), __float2half_rn(v.w)};
    // tile image: [chunk c][mtile][granule g][row r][8 halfs]
    int c  = d >> 7;            // chunk
    int kk = d & 127;           // k within chunk
    int g  = kk >> 3;           // granule
    int mt = b >> 7;            // m-tile
    int r  = b & 127;           // row within tile
    size_t o = ((size_t)(c * 128 + mt)) * (A_TILE / 2) + (size_t)g * 1024 + r * 8 + (kk & 7);
    *reinterpret_cast<uint2*>(&g_Xt[o]) = *reinterpret_cast<uint2*>(h4);
}

__global__ void pack_w(const float* __restrict__ Wi, const float* __restrict__ Wo,
                       const float* __restrict__ Wu, const float* __restrict__ Wfl,
                       const float* __restrict__ Wfs) {
    int i = blockIdx.x * blockDim.x + threadIdx.x;      // over NG*H*(K/4)
    if (i >= NG * H * (K / 4)) return;
    int rw = i / (K / 4);
    int d  = (i % (K / 4)) * 4;
    int gate = rw >> 9, h = rw & 511;
    const float* src;
    if (gate == 0)      src = Wi + (size_t)h * K + d;
    else if (gate == 1) src = Wo + (size_t)h * K + d;
    else if (gate == 2) src = Wu + (size_t)h * K + d;
    else if (d < L)     src = Wfl + (size_t)h * L + d;
    else {
        int dd = d - L; int j = dd >> 9; int hh = dd & 511;
        src = Wfs + (((size_t)(((gate - 3) * 2 + j) * H + h)) << 9) + hh;
    }
    float4 v = *reinterpret_cast<const float4*>(src);
    __half h4[4] = {__float2half_rn(v.x), __float2half_rn(v.y),
                    __float2half_rn(v.z), __float2half_rn(v.w)};
    // tile image: [chunk c][bh-tile][granule g][row rr = gate*64 + h%64][8 halfs]
    int c   = d >> 7;
    int kk  = d & 127;
    int g   = kk >> 3;
    int bht = h >> 6;
    int rr  = gate * 64 + (h & 63);
    size_t o = ((size_t)(c * 8 + bht)) * (B_TILE / 2) + (size_t)g * 2560 + rr * 8 + (kk & 7);
    *reinterpret_cast<uint2*>(&g_Wt[o]) = *reinterpret_cast<uint2*>(h4);
}

// ---- main kernel ----
__global__ __launch_bounds__(THREADS, 1)
void treelstm_mma(const float* __restrict__ ch_c,
                  const float* __restrict__ b_i, const float* __restrict__ b_o,
                  const float* __restrict__ b_u, const float* __restrict__ fbias,
                  float* __restrict__ out) {
    extern __shared__ char smem[];
    const uint32_t sbase = smem_u32(smem);
    const int tid  = threadIdx.x;
    const int wid  = tid >> 5, lane = tid & 31;
    const int wm   = wid & 3;          // 4 m-warps (32 rows each)
    const int wn   = wid >> 2;         // 4 n-warps (80 cols each)
    const int bht  = blockIdx.x;       // h-tile index
    const int mt   = blockIdx.y;       // m-tile index
    const int bh0  = bht * BHh;
    const int bm0  = mt * BM;

    const uint32_t STG0 = sbase;
    const uint32_t STG1 = sbase + STAGE_BYTES;
    const uint32_t mb0  = sbase + 2 * STAGE_BYTES;
    const uint32_t mb1  = mb0 + 16;

    // gmem tile sources
    const char* Abase = reinterpret_cast<const char*>(g_Xt);
    const char* Bbase = reinterpret_cast<const char*>(g_Wt);
    auto Asrc = [&](int c) { return Abase + ((size_t)(c * 128 + mt)) * A_TILE; };
    auto Bsrc = [&](int c) { return Bbase + ((size_t)(c * 8 + bht)) * B_TILE; };

    if (tid == 0) { mbar_init(mb0, 1); mbar_init(mb1, 1); }
    __syncthreads();
    if (tid == 0) {
        mbar_expect(mb0, STAGE_BYTES);
        bulk_cp(STG0 + OFF_A, Asrc(0), A_TILE, mb0);
        bulk_cp(STG0 + OFF_B, Bsrc(0), B_TILE, mb0);
        mbar_expect(mb1, STAGE_BYTES);
        bulk_cp(STG1 + OFF_A, Asrc(1), A_TILE, mb1);
        bulk_cp(STG1 + OFF_B, Bsrc(1), B_TILE, mb1);
    }

    // per-lane ldmatrix base offsets (granule-blocked, no swizzle)
    const int ar  = ((lane >> 3) & 1) * 8 + (lane & 7);
    const uint32_t aBase = (uint32_t)((wm * 32 + ar) * 16) + (uint32_t)(lane >> 4) * AG;
    const int br  = ((lane >> 4) & 1) * 8 + (lane & 7);
    const uint32_t bBase = (uint32_t)((wn * 80 + br) * 16) + (uint32_t)((lane >> 3) & 1) * BG;

    float acc[2][10][4];
    #pragma unroll
    for (int mi = 0; mi < 2; mi++)
        #pragma unroll
        for (int ni = 0; ni < 10; ni++)
            #pragma unroll
            for (int q = 0; q < 4; q++) acc[mi][ni][q] = 0.0f;

    uint32_t ph0 = 0, ph1 = 0;
    for (int k = 0; k < NCHUNK; k++) {
        const int s = k & 1;
        const uint32_t stg = s ? STG1 : STG0;
        if (s) { mbar_wait(mb1, ph1); ph1 ^= 1; }
        else   { mbar_wait(mb0, ph0); ph0 ^= 1; }

        #pragma unroll
        for (int ks = 0; ks < 8; ks++) {           // 8 k16 steps per 128-K chunk
            const uint32_t aAddr = stg + OFF_A + aBase + (uint32_t)(2 * ks) * AG;
            const uint32_t bAddr = stg + OFF_B + bBase + (uint32_t)(2 * ks) * BG;
            uint32_t a[8];
            ldsm4(a + 0, aAddr);
            ldsm4(a + 4, aAddr + 256);             // mi=1: +16 rows * 16B
            #pragma unroll
            for (int np = 0; np < 5; np++) {       // short B live range (reg budget)
                uint32_t b[4];
                ldsm4(b, bAddr + np * 256);
                mma_f16(acc[0][np*2+0], a + 0, b + 0);
                mma_f16(acc[0][np*2+1], a + 0, b + 2);
                mma_f16(acc[1][np*2+0], a + 4, b + 0);
                mma_f16(acc[1][np*2+1], a + 4, b + 2);
            }
        }
        __syncthreads();                            // stage s fully consumed
        if (k + 2 < NCHUNK && tid == 0) {
            const uint32_t mb = s ? mb1 : mb0;
            mbar_expect(mb, STAGE_BYTES);
            bulk_cp(stg + OFF_A, Asrc(k + 2), A_TILE, mb);
            bulk_cp(stg + OFF_B, Bsrc(k + 2), B_TILE, mb);
        }
    }

    // ---- epilogue: recombine gates through SMEM (stride 129 words) ----
    __syncthreads();
    float* gbuf = reinterpret_cast<float*>(smem);   // [320][129]
    #pragma unroll
    for (int mi = 0; mi < 2; mi++)
        #pragma unroll
        for (int ni = 0; ni < 10; ni++) {
            const int m = wm * 32 + mi * 16 + (lane >> 2);
            const int n = wn * 80 + ni * 8 + 2 * (lane & 3);
            gbuf[(size_t)n * 129 + m]           = acc[mi][ni][0];
            gbuf[(size_t)(n + 1) * 129 + m]     = acc[mi][ni][1];
            gbuf[(size_t)n * 129 + m + 8]       = acc[mi][ni][2];
            gbuf[(size_t)(n + 1) * 129 + m + 8] = acc[mi][ni][3];
        }
    __syncthreads();

    for (int idx = tid; idx < BM * BHh; idx += THREADS) {
        const int m = idx >> 6, h = idx & 63;
        const int hg = bh0 + h;
        const int b  = bm0 + m;
        const float vi = gbuf[(size_t)(0 * 64 + h) * 129 + m];
        const float vo = gbuf[(size_t)(1 * 64 + h) * 129 + m];
        const float vu = gbuf[(size_t)(2 * 64 + h) * 129 + m];
        const float v0 = gbuf[(size_t)(3 * 64 + h) * 129 + m];
        const float v1 = gbuf[(size_t)(4 * 64 + h) * 129 + m];
        const float ig = sigmf(vi + __ldg(&b_i[hg]));
        const float og = sigmf(vo + __ldg(&b_o[hg]));
        const float ug = tanhf(vu + __ldg(&b_u[hg]));
        const float f0 = sigmf(v0);
        const float f1 = sigmf(v1);
        const float c0 = ch_c[(size_t)b * H + hg];
        const float c1 = ch_c[(size_t)(Bsz + b) * H + hg];
        const float fb = __ldg(&fbias[hg]);
        const float nc = fmaf(ig, ug, fmaf(f0, c0, fmaf(f1, c1, fb * (c0 + c1))));
        const size_t o = (size_t)b * H + hg;
        out[o] = nc;
        out[(size_t)Bsz * H + o] = tanhf(og * nc);
    }
}

extern "C" void kernel_launch(void* const* d_in, const int* in_sizes, int n_in,
                              void* d_out, int out_size) {
    const float* label = (const float*)d_in[0];
    const float* ch_h  = (const float*)d_in[1];
    const float* ch_c  = (const float*)d_in[2];
    const float* W_i   = (const float*)d_in[3];
    const float* b_i   = (const float*)d_in[4];
    const float* W_o   = (const float*)d_in[5];
    const float* b_o   = (const float*)d_in[6];
    const float* W_u   = (const float*)d_in[7];
    const float* b_u   = (const float*)d_in[8];
    const float* W_fl  = (const float*)d_in[9];
    const float* W_fs  = (const float*)d_in[10];
    const float* fb    = (const float*)d_in[11];

    pack_x<<<(Bsz * (K / 4) + 255) / 256, 256>>>(label, ch_h);
    pack_w<<<(NG * H * (K / 4) + 255) / 256, 256>>>(W_i, W_o, W_u, W_fl, W_fs);

    cudaFuncSetAttribute(treelstm_mma, cudaFuncAttributeMaxDynamicSharedMemorySize, SMEM_TOTAL);
    dim3 grid(H / BHh, Bsz / BM);   // (8, 128)
    treelstm_mma<<<grid, THREADS, SMEM_TOTAL>>>(ch_c, b_i, b_o, b_u, fb, (float*)d_out);
}